// round 16
// baseline (speedup 1.0000x reference)
#include <cuda_runtime.h>
#include <cstdint>
#include <math.h>

// Problem constants
#define B_  4
#define T_  4096
#define D_  2048
#define M_  512

#define CHUNK 32
#define NCH   (T_ / CHUNK)          // 128

// Scratch
__device__ __align__(1024) float    g_v[(size_t)B_ * T_ * M_];          // v fp32
__device__ __align__(1024) uint32_t g_wv16[(size_t)B_ * T_ * M_ / 2];   // wv fp16
__device__ __align__(1024) uint32_t g_x16[(size_t)B_ * T_ * D_ / 2];    // x fp16
__device__ __align__(1024) uint32_t g_wv_w16[(size_t)M_ * D_ / 2];      // Wv fp16
__device__ __align__(1024) uint32_t g_wg_w16[(size_t)D_ * (D_ + M_) / 2]; // Wg fp16
__device__ float g_part[B_ * NCH * M_];
__device__ float g_init[B_ * NCH * M_];

// ---------------------------------------------------------------------------
// helpers
// ---------------------------------------------------------------------------
__device__ __forceinline__ uint32_t smem_u32(const void* p) {
    uint32_t a;
    asm("{ .reg .u64 t; cvta.to.shared.u64 t, %1; cvt.u32.u64 %0, t; }" : "=r"(a) : "l"(p));
    return a;
}
__device__ __forceinline__ uint32_t pack_h2(float lo, float hi) {
    uint32_t r;
    asm("cvt.rn.f16x2.f32 %0, %1, %2;" : "=r"(r) : "f"(hi), "f"(lo));
    return r;
}
#define CP_ASYNC(dst_u32, src_ptr) \
    asm volatile("cp.async.cg.shared.global [%0], [%1], 16;" :: "r"(dst_u32), "l"(src_ptr) : "memory")

#define MBAR_INIT(addr, cnt) \
    asm volatile("mbarrier.init.shared.b64 [%0], %1;" :: "r"(addr), "r"((uint32_t)(cnt)) : "memory")
#define MBAR_ARRIVE(addr) \
    asm volatile("mbarrier.arrive.shared.b64 _, [%0];" :: "r"(addr) : "memory")
// .noinc: do NOT bump expected count — each loader thread contributes exactly
// one arrival (triggered when its prior cp.asyncs complete). full init = 32.
#define CPASYNC_MBAR_ARRIVE(addr) \
    asm volatile("cp.async.mbarrier.arrive.noinc.shared.b64 [%0];" :: "r"(addr) : "memory")

// parity wait (acquire), spin until pass
__device__ __forceinline__ void mbar_wait(uint32_t addr, uint32_t parity) {
    asm volatile(
        "{\n\t"
        ".reg .pred P1;\n\t"
        "WAIT_LOOP_%=:\n\t"
        "mbarrier.try_wait.parity.acquire.cta.shared::cta.b64 P1, [%0], %1, 0x989680;\n\t"
        "@P1 bra.uni WAIT_DONE_%=;\n\t"
        "bra.uni WAIT_LOOP_%=;\n\t"
        "WAIT_DONE_%=:\n\t"
        "}"
        :: "r"(addr), "r"(parity) : "memory");
}

#define MMA_F16(d, a0, a1, a2, a3, b0, b1) \
    asm volatile("mma.sync.aligned.m16n8k16.row.col.f32.f16.f16.f32 " \
        "{%0,%1,%2,%3}, {%4,%5,%6,%7}, {%8,%9}, {%0,%1,%2,%3};" \
        : "+f"((d)[0]), "+f"((d)[1]), "+f"((d)[2]), "+f"((d)[3]) \
        : "r"(a0), "r"(a1), "r"(a2), "r"(a3), "r"(b0), "r"(b1))

#define LDSM4(r, addr) \
    asm volatile("ldmatrix.sync.aligned.m8n8.x4.shared.b16 {%0,%1,%2,%3}, [%4];" \
        : "=r"((r)[0]), "=r"((r)[1]), "=r"((r)[2]), "=r"((r)[3]) : "r"(addr))

// ---------------------------------------------------------------------------
// Warp-specialized fp16 GEMM (fp32 accumulate):
//   C[N, Mo] = concat(A1h,A2h)[N, K] * Bh[Mo, K]^T (+bias, +resid)
// 288 threads: warps 0-7 consumers (64x32 tiles of 128x128), warp 8 loader.
// 4-stage mbarrier pipeline, BK=64. No __syncthreads in mainloop.
// ---------------------------------------------------------------------------
#define BM 128
#define BN 128
#define BK 64
#define NTHREADS 288
#define STAGES 4
#define LDHW 36                       // u32 per fp16 row (32 data + 4 pad) => 144B
#define BUFU32 (256 * LDHW)           // 9216 u32 = 36 KB per stage
#define STG0 64                       // stage data starts at u32 index 64 (256B)
#define SMEM_BYTES (STG0 * 4 + STAGES * BUFU32 * 4)   // 256 + 147456 = 147712

extern __shared__ uint32_t hsm[];

__global__ __launch_bounds__(NTHREADS, 1)
void gemm_h16(const uint32_t* __restrict__ A1h, int K1,
              const uint32_t* __restrict__ A2h, int K2,
              const uint32_t* __restrict__ Bh,
              const float* __restrict__ bias,
              const float* __restrict__ resid,
              float* __restrict__ C, int ldC)
{
    const int K   = K1 + K2;
    const int NCT = K / BK;
    const int tid = threadIdx.x;
    const int wid  = tid >> 5;
    const int lane = tid & 31;
    const int n0 = blockIdx.y * BM;
    const int m0 = blockIdx.x * BN;

    const uint32_t sbase = smem_u32(hsm);
    // barriers: full[s] at sbase + s*16, empty[s] at sbase + s*16 + 8
    if (tid == 0) {
        #pragma unroll
        for (int s = 0; s < STAGES; ++s) {
            MBAR_INIT(sbase + s * 16,     32);   // full: 32 loader threads (.noinc arrivals)
            MBAR_INIT(sbase + s * 16 + 8, 256);  // empty: 256 consumer threads
        }
    }
    __syncthreads();

    const int k1u = K1 >> 1, k2u = K2 >> 1, ku = K >> 1;

    if (wid == 8) {
        // ---------------- loader warp ----------------
        const int lq = lane & 7;        // 16B quad within 128B row
        const int rg = lane >> 3;       // 0..3
        int ps = 0, pph = 1;            // producer cursor (phase starts flipped)
        for (int c = 0; c < NCT; ++c) {
            mbar_wait(sbase + ps * 16 + 8, pph);   // wait empty[ps]
            const int k0u = c * (BK / 2);
            uint32_t* dst = hsm + STG0 + ps * BUFU32;
            #pragma unroll 8
            for (int i = 0; i < 64; ++i) {
                int row = rg + 4 * i;               // 0..255
                const uint32_t* g;
                if (row < BM) {
                    int gr = n0 + row;
                    g = (k0u < k1u)
                        ? A1h + (size_t)gr * k1u + k0u + lq * 4
                        : A2h + (size_t)gr * k2u + (k0u - k1u) + lq * 4;
                } else {
                    int gr = m0 + (row - BM);
                    g = Bh + (size_t)gr * ku + k0u + lq * 4;
                }
                CP_ASYNC(smem_u32(dst + row * LDHW + lq * 4), g);
            }
            CPASYNC_MBAR_ARRIVE(sbase + ps * 16);  // arrive full[ps] when cp.asyncs land
            if (++ps == STAGES) { ps = 0; pph ^= 1; }
        }
        return;
    }

    // ---------------- consumer warps (0-7) ----------------
    const int wm = (wid >> 2) * 64;
    const int wn = (wid & 3) * 32;
    const int grp = lane >> 3;
    const int r8  = lane & 7;
    const int aoff = (wm + (grp & 1) * 8 + r8) * LDHW + (grp >> 1) * 4;
    const int boff = (BM + wn + (grp >> 1) * 8 + r8) * LDHW + (grp & 1) * 4;
    uint32_t abs_[STAGES], bbs_[STAGES];
    #pragma unroll
    for (int s = 0; s < STAGES; ++s) {
        abs_[s] = smem_u32(hsm + STG0 + s * BUFU32 + aoff);
        bbs_[s] = smem_u32(hsm + STG0 + s * BUFU32 + boff);
    }

    float acc[4][4][4];
    #pragma unroll
    for (int mi = 0; mi < 4; ++mi)
        #pragma unroll
        for (int nj = 0; nj < 4; ++nj)
            #pragma unroll
            for (int q = 0; q < 4; ++q) acc[mi][nj][q] = 0.0f;

    int cs = 0, cph = 0;                // consumer cursor
    for (int kt = 0; kt < NCT; ++kt) {
        mbar_wait(sbase + cs * 16, cph);     // wait full[cs] (acquire)
        const uint32_t ab = abs_[cs];
        const uint32_t bb = bbs_[cs];

        #pragma unroll
        for (int ks = 0; ks < 4; ++ks) {
            uint32_t af[4][4], bf[2][4];
            #pragma unroll
            for (int mi = 0; mi < 4; ++mi)
                LDSM4(af[mi], ab + (mi * 16 * LDHW + ks * 8) * 4);
            #pragma unroll
            for (int njp = 0; njp < 2; ++njp)
                LDSM4(bf[njp], bb + (njp * 16 * LDHW + ks * 8) * 4);
            #pragma unroll
            for (int mi = 0; mi < 4; ++mi)
                #pragma unroll
                for (int nj = 0; nj < 4; ++nj)
                    MMA_F16(acc[mi][nj],
                            af[mi][0], af[mi][1], af[mi][2], af[mi][3],
                            bf[nj >> 1][(nj & 1) * 2], bf[nj >> 1][(nj & 1) * 2 + 1]);
        }
        MBAR_ARRIVE(sbase + cs * 16 + 8);    // empty[cs]
        if (++cs == STAGES) { cs = 0; cph ^= 1; }
    }

    // ---- epilogue
    #pragma unroll
    for (int mi = 0; mi < 4; ++mi) {
        const int rbase = n0 + wm + mi * 16 + (lane >> 2);
        #pragma unroll
        for (int nj = 0; nj < 4; ++nj) {
            const int col = m0 + wn + nj * 8 + 2 * (lane & 3);
            float2 bb2 = *(const float2*)(bias + col);
            #pragma unroll
            for (int h = 0; h < 2; ++h) {
                const int r = rbase + h * 8;
                float2 v;
                v.x = acc[mi][nj][2 * h + 0] + bb2.x;
                v.y = acc[mi][nj][2 * h + 1] + bb2.y;
                size_t off = (size_t)r * ldC + col;
                if (resid) {
                    float2 rr = *(const float2*)(resid + off);
                    v.x += rr.x; v.y += rr.y;
                }
                *(float2*)(C + off) = v;
            }
        }
    }
}

// ---------------------------------------------------------------------------
// fp32 -> fp16 conversion (grid-stride, float4 -> uint2)
// ---------------------------------------------------------------------------
__global__ void f32_to_f16(const float4* __restrict__ src,
                           uint2* __restrict__ dst, int n4)
{
    int stride = gridDim.x * blockDim.x;
    for (int i = blockIdx.x * blockDim.x + threadIdx.x; i < n4; i += stride) {
        float4 v = src[i];
        uint2 h;
        h.x = pack_h2(v.x, v.y);
        h.y = pack_h2(v.z, v.w);
        dst[i] = h;
    }
}

// ---------------------------------------------------------------------------
// Recurrence: chunked parallel scan, float4 vectorized over m
// ---------------------------------------------------------------------------
__device__ __forceinline__ float4 sigmoid4(float4 a) {
    float4 r;
    r.x = 1.0f / (1.0f + expf(-a.x));
    r.y = 1.0f / (1.0f + expf(-a.y));
    r.z = 1.0f / (1.0f + expf(-a.z));
    r.w = 1.0f / (1.0f + expf(-a.w));
    return r;
}

__global__ void rec_partial(const float* __restrict__ time_decay)
{
    int id = blockIdx.x * blockDim.x + threadIdx.x;
    if (id >= B_ * NCH * M_ / 4) return;
    int m4 = id % (M_ / 4);
    int ch = (id / (M_ / 4)) % NCH;
    int b  = id / ((M_ / 4) * NCH);

    float4 sd = sigmoid4(*(const float4*)(time_decay + m4 * 4));
    float4 dec = make_float4(sd.x * 0.9f + 0.1f, sd.y * 0.9f + 0.1f,
                             sd.z * 0.9f + 0.1f, sd.w * 0.9f + 0.1f);
    const float4* vp = (const float4*)(g_v + ((size_t)b * T_ + (size_t)ch * CHUNK) * M_) + m4;
    float4 s = make_float4(0.f, 0.f, 0.f, 0.f);
    #pragma unroll 8
    for (int t = 0; t < CHUNK; ++t) {
        float4 v = vp[(size_t)t * (M_ / 4)];
        s.x = s.x * dec.x + v.x;
        s.y = s.y * dec.y + v.y;
        s.z = s.z * dec.z + v.z;
        s.w = s.w * dec.w + v.w;
    }
    ((float4*)g_part)[id] = s;
}

__global__ void rec_combine(const float* __restrict__ memory_state,
                            const float* __restrict__ time_decay,
                            float* __restrict__ next_mem)
{
    int id = blockIdx.x * blockDim.x + threadIdx.x;
    if (id >= B_ * M_) return;
    int m = id % M_;
    int b = id / M_;

    float dec  = 1.0f / (1.0f + expf(-time_decay[m])) * 0.9f + 0.1f;
    float decC = powf(dec, (float)CHUNK);
    float s = memory_state[id];
    #pragma unroll 4
    for (int ch = 0; ch < NCH; ++ch) {
        int idx = (b * NCH + ch) * M_ + m;
        g_init[idx] = s;
        s = s * decC + g_part[idx];
    }
    next_mem[id] = s;
}

__global__ void rec_apply(const float* __restrict__ time_decay,
                          const float* __restrict__ time_first)
{
    int id = blockIdx.x * blockDim.x + threadIdx.x;
    if (id >= B_ * NCH * M_ / 4) return;
    int m4 = id % (M_ / 4);
    int ch = (id / (M_ / 4)) % NCH;
    int b  = id / ((M_ / 4) * NCH);

    float4 sd = sigmoid4(*(const float4*)(time_decay + m4 * 4));
    float4 dec = make_float4(sd.x * 0.9f + 0.1f, sd.y * 0.9f + 0.1f,
                             sd.z * 0.9f + 0.1f, sd.w * 0.9f + 0.1f);
    float4 first = sigmoid4(*(const float4*)(time_first + m4 * 4));
    float4 s = ((const float4*)g_init)[id];

    const float4* vp = (const float4*)(g_v + ((size_t)b * T_ + (size_t)ch * CHUNK) * M_) + m4;
    uint2* wp = (uint2*)(g_wv16 + ((size_t)b * T_ + (size_t)ch * CHUNK) * (M_ / 2)) + m4;
    #pragma unroll 4
    for (int t = 0; t < CHUNK; ++t) {
        float4 v = vp[(size_t)t * (M_ / 4)];
        uint2 h;
        h.x = pack_h2(v.x + s.x * first.x, v.y + s.y * first.y);
        h.y = pack_h2(v.z + s.z * first.z, v.w + s.w * first.w);
        wp[(size_t)t * (M_ / 4)] = h;
        s.x = s.x * dec.x + v.x;
        s.y = s.y * dec.y + v.y;
        s.z = s.z * dec.z + v.z;
        s.w = s.w * dec.w + v.w;
    }
}

// ---------------------------------------------------------------------------
extern "C" void kernel_launch(void* const* d_in, const int* in_sizes, int n_in,
                              void* d_out, int out_size)
{
    const float* x   = (const float*)d_in[0];  // [B, T, D]
    const float* mem = (const float*)d_in[1];  // [B, M]
    const float* Wv  = (const float*)d_in[2];  // [M, D]
    const float* bv  = (const float*)d_in[3];  // [M]
    const float* Wg  = (const float*)d_in[4];  // [D, D+M]
    const float* bg  = (const float*)d_in[5];  // [D]
    const float* td  = (const float*)d_in[6];  // [M]
    const float* tf  = (const float*)d_in[7];  // [M]
    float* out = (float*)d_out;                // [B,T,D], then [B,M] next_memory

    float *v_ptr; uint32_t *x16, *wv16, *wvw16, *wgw16;
    cudaGetSymbolAddress((void**)&v_ptr,  g_v);
    cudaGetSymbolAddress((void**)&x16,    g_x16);
    cudaGetSymbolAddress((void**)&wv16,   g_wv16);
    cudaGetSymbolAddress((void**)&wvw16,  g_wv_w16);
    cudaGetSymbolAddress((void**)&wgw16,  g_wg_w16);

    cudaFuncSetAttribute(gemm_h16, cudaFuncAttributeMaxDynamicSharedMemorySize,
                         SMEM_BYTES);

    const int N = B_ * T_;   // 16384

    // Stage 0: fp32 -> fp16 conversions
    f32_to_f16<<<2048, 256>>>((const float4*)x,  (uint2*)x16,   N * D_ / 4);
    f32_to_f16<<<512,  256>>>((const float4*)Wv, (uint2*)wvw16, M_ * D_ / 4);
    f32_to_f16<<<1024, 256>>>((const float4*)Wg, (uint2*)wgw16, D_ * (D_ + M_) / 4);

    // Stage 1: v = x @ Wv^T + bv   -> g_v [N, 512] (fp32)
    {
        dim3 grid(M_ / BN, N / BM);   // (4, 128)
        gemm_h16<<<grid, NTHREADS, SMEM_BYTES>>>(x16, D_, nullptr, 0,
                                                 wvw16, bv, nullptr, v_ptr, M_);
    }

    // Stage 2: chunked-scan recurrence; wv emitted as fp16
    {
        float* next_mem = out + (size_t)B_ * T_ * D_;
        int n1 = B_ * NCH * M_ / 4;   // 65536
        rec_partial<<<(n1 + 255) / 256, 256>>>(td);
        rec_combine<<<(B_ * M_ + 127) / 128, 128>>>(mem, td, next_mem);
        rec_apply<<<(n1 + 255) / 256, 256>>>(td, tf);
    }

    // Stage 3: out = x + concat(x, wv) @ Wg^T + bg   -> out [N, 2048]
    {
        dim3 grid(D_ / BN, N / BM);   // (16, 128)
        gemm_h16<<<grid, NTHREADS, SMEM_BYTES>>>(x16, D_, wv16, M_,
                                                 wgw16, bg, x, out, D_);
    }
}

// round 17
// speedup vs baseline: 3.1952x; 3.1952x over previous
#include <cuda_runtime.h>
#include <cstdint>
#include <math.h>

// Problem constants
#define B_  4
#define T_  4096
#define D_  2048
#define M_  512

#define CHUNK 32
#define NCH   (T_ / CHUNK)          // 128

// Scratch
__device__ __align__(1024) float    g_v[(size_t)B_ * T_ * M_];          // v fp32
__device__ __align__(1024) uint32_t g_wv16[(size_t)B_ * T_ * M_ / 2];   // wv fp16
__device__ __align__(1024) uint32_t g_x16[(size_t)B_ * T_ * D_ / 2];    // x fp16
__device__ __align__(1024) uint32_t g_wv_w16[(size_t)M_ * D_ / 2];      // Wv fp16
__device__ __align__(1024) uint32_t g_wg_w16[(size_t)D_ * (D_ + M_) / 2]; // Wg fp16
__device__ float g_part[B_ * NCH * M_];
__device__ float g_init[B_ * NCH * M_];

// ---------------------------------------------------------------------------
// helpers
// ---------------------------------------------------------------------------
__device__ __forceinline__ uint32_t smem_u32(const void* p) {
    uint32_t a;
    asm("{ .reg .u64 t; cvta.to.shared.u64 t, %1; cvt.u32.u64 %0, t; }" : "=r"(a) : "l"(p));
    return a;
}
__device__ __forceinline__ uint32_t pack_h2(float lo, float hi) {
    uint32_t r;
    asm("cvt.rn.f16x2.f32 %0, %1, %2;" : "=r"(r) : "f"(hi), "f"(lo));
    return r;
}
#define CP_ASYNC(dst_u32, src_ptr) \
    asm volatile("cp.async.cg.shared.global [%0], [%1], 16;" :: "r"(dst_u32), "l"(src_ptr) : "memory")
#define CP_COMMIT() asm volatile("cp.async.commit_group;" ::: "memory")
#define CP_WAIT(n)  asm volatile("cp.async.wait_group %0;" :: "n"(n) : "memory")

#define MMA_F16(d, a0, a1, a2, a3, b0, b1) \
    asm volatile("mma.sync.aligned.m16n8k16.row.col.f32.f16.f16.f32 " \
        "{%0,%1,%2,%3}, {%4,%5,%6,%7}, {%8,%9}, {%0,%1,%2,%3};" \
        : "+f"((d)[0]), "+f"((d)[1]), "+f"((d)[2]), "+f"((d)[3]) \
        : "r"(a0), "r"(a1), "r"(a2), "r"(a3), "r"(b0), "r"(b1))

#define LDSM4(r, addr) \
    asm volatile("ldmatrix.sync.aligned.m8n8.x4.shared.b16 {%0,%1,%2,%3}, [%4];" \
        : "=r"((r)[0]), "=r"((r)[1]), "=r"((r)[2]), "=r"((r)[3]) : "r"(addr))

// ---------------------------------------------------------------------------
// fp16 GEMM (fp32 accumulate): C[N, Mo] = concat(A1h,A2h)[N, K] * Bh[Mo, K]^T
//   (+bias, +resid). Templated tile height:
//   MI=4: CTA 128x128, warp 64x32, occ 2 (the gate config — at HMMA ceiling)
//   MI=2: CTA  64x128, warp 32x32, occ 3 (v config — fixes wave quantization)
// BK=64, 2-stage cp.async double buffer, one __syncthreads per ktile.
// ---------------------------------------------------------------------------
#define BN 128
#define BK 64
#define NTHREADS 256
#define LDHW 36                       // u32 per fp16 row (32 data + 4 pad) => 144B

template<int MI>
__global__ __launch_bounds__(NTHREADS, (MI == 4) ? 2 : 3)
void gemm_h16(const uint32_t* __restrict__ A1h, int K1,
              const uint32_t* __restrict__ A2h, int K2,
              const uint32_t* __restrict__ Bh,
              const float* __restrict__ bias,
              const float* __restrict__ resid,
              float* __restrict__ C, int ldC)
{
    constexpr int BMt   = MI * 32;            // 128 or 64
    constexpr int ROWS  = BMt + BN;           // 256 or 192
    constexpr int BUF   = ROWS * LDHW;        // u32 per stage

    extern __shared__ uint32_t hsm[];

    const int K   = K1 + K2;
    const int NCT = K / BK;
    const int tid = threadIdx.x;
    const int wid  = tid >> 5;
    const int lane = tid & 31;
    const int n0 = blockIdx.y * BMt;
    const int m0 = blockIdx.x * BN;
    const int wm = (wid >> 2) * (MI * 16);
    const int wn = (wid & 3) * 32;

    // loader mapping: ROWS*8 16B transfers/stage
    const int lrow = tid >> 3;        // 0..31 (+32 per it)
    const int lq   = tid & 7;         // 16B quad within 128B row

    // ldmatrix lane mapping (base offsets hoisted per stage)
    const int grp = lane >> 3;
    const int r8  = lane & 7;
    const int aoff = (wm + (grp & 1) * 8 + r8) * LDHW + (grp >> 1) * 4;
    const int boff = (BMt + wn + (grp >> 1) * 8 + r8) * LDHW + (grp & 1) * 4;
    const uint32_t ab0 = smem_u32(hsm + aoff);
    const uint32_t bb0 = smem_u32(hsm + boff);
    const uint32_t ab1 = smem_u32(hsm + BUF + aoff);
    const uint32_t bb1 = smem_u32(hsm + BUF + boff);

    float acc[MI][4][4];
    #pragma unroll
    for (int mi = 0; mi < MI; ++mi)
        #pragma unroll
        for (int nj = 0; nj < 4; ++nj)
            #pragma unroll
            for (int q = 0; q < 4; ++q) acc[mi][nj][q] = 0.0f;

    // strides in u32 (half2) units
    const int k1u = K1 >> 1, k2u = K2 >> 1, ku = K >> 1;

    auto ldg = [&](int c) {
        const int k0u = c * (BK / 2);
        uint32_t* dst = hsm + (c & 1) * BUF;
        #pragma unroll
        for (int it = 0; it < ROWS / 32; ++it) {
            int row = lrow + it * 32;               // 0..ROWS-1
            const uint32_t* g;
            if (row < BMt) {
                int gr = n0 + row;
                g = (k0u < k1u)
                    ? A1h + (size_t)gr * k1u + k0u + lq * 4
                    : A2h + (size_t)gr * k2u + (k0u - k1u) + lq * 4;
            } else {
                int gr = m0 + (row - BMt);
                g = Bh + (size_t)gr * ku + k0u + lq * 4;
            }
            CP_ASYNC(smem_u32(dst + row * LDHW + lq * 4), g);
        }
    };

    // ---- prologue
    ldg(0); CP_COMMIT();

    // ---- main loop: one barrier + one wait per BK=64
    for (int kt = 0; kt < NCT; ++kt) {
        CP_WAIT(0);
        __syncthreads();
        if (kt + 1 < NCT) ldg(kt + 1);
        CP_COMMIT();

        const uint32_t ab = (kt & 1) ? ab1 : ab0;
        const uint32_t bb = (kt & 1) ? bb1 : bb0;

        #pragma unroll
        for (int ks = 0; ks < 4; ++ks) {
            uint32_t af[MI][4], bf[2][4];
            #pragma unroll
            for (int mi = 0; mi < MI; ++mi)
                LDSM4(af[mi], ab + (mi * 16 * LDHW + ks * 8) * 4);
            #pragma unroll
            for (int njp = 0; njp < 2; ++njp)
                LDSM4(bf[njp], bb + (njp * 16 * LDHW + ks * 8) * 4);
            #pragma unroll
            for (int mi = 0; mi < MI; ++mi)
                #pragma unroll
                for (int nj = 0; nj < 4; ++nj)
                    MMA_F16(acc[mi][nj],
                            af[mi][0], af[mi][1], af[mi][2], af[mi][3],
                            bf[nj >> 1][(nj & 1) * 2], bf[nj >> 1][(nj & 1) * 2 + 1]);
        }
    }

    // ---- epilogue
    #pragma unroll
    for (int mi = 0; mi < MI; ++mi) {
        const int rbase = n0 + wm + mi * 16 + (lane >> 2);
        #pragma unroll
        for (int nj = 0; nj < 4; ++nj) {
            const int col = m0 + wn + nj * 8 + 2 * (lane & 3);
            float2 bb2 = *(const float2*)(bias + col);
            #pragma unroll
            for (int h = 0; h < 2; ++h) {
                const int r = rbase + h * 8;
                float2 v;
                v.x = acc[mi][nj][2 * h + 0] + bb2.x;
                v.y = acc[mi][nj][2 * h + 1] + bb2.y;
                size_t off = (size_t)r * ldC + col;
                if (resid) {
                    float2 rr = *(const float2*)(resid + off);
                    v.x += rr.x; v.y += rr.y;
                }
                *(float2*)(C + off) = v;
            }
        }
    }
}

// ---------------------------------------------------------------------------
// fp32 -> fp16 conversion (grid-stride, float4 -> uint2)
// ---------------------------------------------------------------------------
__global__ void f32_to_f16(const float4* __restrict__ src,
                           uint2* __restrict__ dst, int n4)
{
    int stride = gridDim.x * blockDim.x;
    for (int i = blockIdx.x * blockDim.x + threadIdx.x; i < n4; i += stride) {
        float4 v = src[i];
        uint2 h;
        h.x = pack_h2(v.x, v.y);
        h.y = pack_h2(v.z, v.w);
        dst[i] = h;
    }
}

// ---------------------------------------------------------------------------
// Recurrence: chunked parallel scan, float4 vectorized over m
// ---------------------------------------------------------------------------
__device__ __forceinline__ float4 sigmoid4(float4 a) {
    float4 r;
    r.x = 1.0f / (1.0f + expf(-a.x));
    r.y = 1.0f / (1.0f + expf(-a.y));
    r.z = 1.0f / (1.0f + expf(-a.z));
    r.w = 1.0f / (1.0f + expf(-a.w));
    return r;
}

__global__ void rec_partial(const float* __restrict__ time_decay)
{
    int id = blockIdx.x * blockDim.x + threadIdx.x;
    if (id >= B_ * NCH * M_ / 4) return;
    int m4 = id % (M_ / 4);
    int ch = (id / (M_ / 4)) % NCH;
    int b  = id / ((M_ / 4) * NCH);

    float4 sd = sigmoid4(*(const float4*)(time_decay + m4 * 4));
    float4 dec = make_float4(sd.x * 0.9f + 0.1f, sd.y * 0.9f + 0.1f,
                             sd.z * 0.9f + 0.1f, sd.w * 0.9f + 0.1f);
    const float4* vp = (const float4*)(g_v + ((size_t)b * T_ + (size_t)ch * CHUNK) * M_) + m4;
    float4 s = make_float4(0.f, 0.f, 0.f, 0.f);
    #pragma unroll 8
    for (int t = 0; t < CHUNK; ++t) {
        float4 v = vp[(size_t)t * (M_ / 4)];
        s.x = s.x * dec.x + v.x;
        s.y = s.y * dec.y + v.y;
        s.z = s.z * dec.z + v.z;
        s.w = s.w * dec.w + v.w;
    }
    ((float4*)g_part)[id] = s;
}

__global__ void rec_combine(const float* __restrict__ memory_state,
                            const float* __restrict__ time_decay,
                            float* __restrict__ next_mem)
{
    int id = blockIdx.x * blockDim.x + threadIdx.x;
    if (id >= B_ * M_) return;
    int m = id % M_;
    int b = id / M_;

    float dec  = 1.0f / (1.0f + expf(-time_decay[m])) * 0.9f + 0.1f;
    float decC = powf(dec, (float)CHUNK);
    float s = memory_state[id];
    #pragma unroll 4
    for (int ch = 0; ch < NCH; ++ch) {
        int idx = (b * NCH + ch) * M_ + m;
        g_init[idx] = s;
        s = s * decC + g_part[idx];
    }
    next_mem[id] = s;
}

__global__ void rec_apply(const float* __restrict__ time_decay,
                          const float* __restrict__ time_first)
{
    int id = blockIdx.x * blockDim.x + threadIdx.x;
    if (id >= B_ * NCH * M_ / 4) return;
    int m4 = id % (M_ / 4);
    int ch = (id / (M_ / 4)) % NCH;
    int b  = id / ((M_ / 4) * NCH);

    float4 sd = sigmoid4(*(const float4*)(time_decay + m4 * 4));
    float4 dec = make_float4(sd.x * 0.9f + 0.1f, sd.y * 0.9f + 0.1f,
                             sd.z * 0.9f + 0.1f, sd.w * 0.9f + 0.1f);
    float4 first = sigmoid4(*(const float4*)(time_first + m4 * 4));
    float4 s = ((const float4*)g_init)[id];

    const float4* vp = (const float4*)(g_v + ((size_t)b * T_ + (size_t)ch * CHUNK) * M_) + m4;
    uint2* wp = (uint2*)(g_wv16 + ((size_t)b * T_ + (size_t)ch * CHUNK) * (M_ / 2)) + m4;
    #pragma unroll 4
    for (int t = 0; t < CHUNK; ++t) {
        float4 v = vp[(size_t)t * (M_ / 4)];
        uint2 h;
        h.x = pack_h2(v.x + s.x * first.x, v.y + s.y * first.y);
        h.y = pack_h2(v.z + s.z * first.z, v.w + s.w * first.w);
        wp[(size_t)t * (M_ / 4)] = h;
        s.x = s.x * dec.x + v.x;
        s.y = s.y * dec.y + v.y;
        s.z = s.z * dec.z + v.z;
        s.w = s.w * dec.w + v.w;
    }
}

// ---------------------------------------------------------------------------
extern "C" void kernel_launch(void* const* d_in, const int* in_sizes, int n_in,
                              void* d_out, int out_size)
{
    const float* x   = (const float*)d_in[0];  // [B, T, D]
    const float* mem = (const float*)d_in[1];  // [B, M]
    const float* Wv  = (const float*)d_in[2];  // [M, D]
    const float* bv  = (const float*)d_in[3];  // [M]
    const float* Wg  = (const float*)d_in[4];  // [D, D+M]
    const float* bg  = (const float*)d_in[5];  // [D]
    const float* td  = (const float*)d_in[6];  // [M]
    const float* tf  = (const float*)d_in[7];  // [M]
    float* out = (float*)d_out;                // [B,T,D], then [B,M] next_memory

    float *v_ptr; uint32_t *x16, *wv16, *wvw16, *wgw16;
    cudaGetSymbolAddress((void**)&v_ptr,  g_v);
    cudaGetSymbolAddress((void**)&x16,    g_x16);
    cudaGetSymbolAddress((void**)&wv16,   g_wv16);
    cudaGetSymbolAddress((void**)&wvw16,  g_wv_w16);
    cudaGetSymbolAddress((void**)&wgw16,  g_wg_w16);

    const int SMEM_GATE = 2 * (256 * LDHW) * 4;   // 73728
    const int SMEM_V    = 2 * (192 * LDHW) * 4;   // 55296
    cudaFuncSetAttribute(gemm_h16<4>, cudaFuncAttributeMaxDynamicSharedMemorySize,
                         SMEM_GATE);
    cudaFuncSetAttribute(gemm_h16<2>, cudaFuncAttributeMaxDynamicSharedMemorySize,
                         SMEM_V);

    const int N = B_ * T_;   // 16384

    // Stage 0: fp32 -> fp16 conversions
    f32_to_f16<<<2048, 256>>>((const float4*)x,  (uint2*)x16,   N * D_ / 4);
    f32_to_f16<<<512,  256>>>((const float4*)Wv, (uint2*)wvw16, M_ * D_ / 4);
    f32_to_f16<<<1024, 256>>>((const float4*)Wg, (uint2*)wgw16, D_ * (D_ + M_) / 4);

    // Stage 1: v = x @ Wv^T + bv   -> g_v [N, 512] (fp32); BM=64 config
    {
        dim3 grid(M_ / BN, N / 64);   // (4, 256) = 1024 CTAs
        gemm_h16<2><<<grid, NTHREADS, SMEM_V>>>(x16, D_, nullptr, 0,
                                                wvw16, bv, nullptr, v_ptr, M_);
    }

    // Stage 2: chunked-scan recurrence; wv emitted as fp16
    {
        float* next_mem = out + (size_t)B_ * T_ * D_;
        int n1 = B_ * NCH * M_ / 4;   // 65536
        rec_partial<<<(n1 + 255) / 256, 256>>>(td);
        rec_combine<<<(B_ * M_ + 127) / 128, 128>>>(mem, td, next_mem);
        rec_apply<<<(n1 + 255) / 256, 256>>>(td, tf);
    }

    // Stage 3: out = x + concat(x, wv) @ Wg^T + bg   -> out [N, 2048]; BM=128
    {
        dim3 grid(D_ / BN, N / 128);   // (16, 128) = 2048 CTAs
        gemm_h16<4><<<grid, NTHREADS, SMEM_GATE>>>(x16, D_, wv16, M_,
                                                   wgw16, bg, x, out, D_);
    }
}